// round 10
// baseline (speedup 1.0000x reference)
#include <cuda_runtime.h>
#include <cuda_fp16.h>
#include <cstdint>

#define D    128
#define HS   128
#define MAXG 16384
#define AP   136      // padded smem row pitch in fp16 elems
#define TILE 128      // rows per tile
#define NSM  148
#define NTHR 384      // 8 consumer warps + 4 producer warps

// ---------------- device scratch ----------------
__device__ float g_den[MAXG];
__device__ int   g_is64;
__device__ __align__(16) __half g_Wh[HS * D];

// ---------------- smem layout (bytes) ----------------
#define SM_SB    0                       // 128 f32 bias
#define SM_SW    512                     // 128 f32 w_score
#define SM_SE    1024                    // 2 slots x 256 f32 = 2048
#define SM_POOL  3072                    // 128 f32 exp(e)
#define SM_SBAT  3584                    // 4 slots x 128 int = 2048
#define SM_BHI   5632                    // 128 x AP fp16 = 34816
#define SM_ABUF  40448                   // 4 x 34816 = 139264
#define ABUF_SZ  34816
#define SMEM1_TOTAL (SM_ABUF + 4 * ABUF_SZ)   // 179712

// ---------------- helpers ----------------
__device__ __forceinline__ unsigned su32(const void* p) {
    return (unsigned)__cvta_generic_to_shared(p);
}
__device__ __forceinline__ float tanh_approx(float x) {
    float y;
    asm("tanh.approx.f32 %0, %1;" : "=f"(y) : "f"(x));
    return y;
}

#define LDSM4(r0, r1, r2, r3, addr)                                          \
    asm volatile("ldmatrix.sync.aligned.m8n8.x4.shared.b16 {%0,%1,%2,%3}, [%4];" \
                 : "=r"(r0), "=r"(r1), "=r"(r2), "=r"(r3) : "r"(addr))

#define MMA16816F(c, a0, a1, a2, a3, b0, b1)                                 \
    asm volatile(                                                            \
        "mma.sync.aligned.m16n8k16.row.col.f32.f16.f16.f32 "                 \
        "{%0,%1,%2,%3},{%4,%5,%6,%7},{%8,%9},{%0,%1,%2,%3};"                 \
        : "+f"(c[0]), "+f"(c[1]), "+f"(c[2]), "+f"(c[3])                     \
        : "r"(a0), "r"(a1), "r"(a2), "r"(a3), "r"(b0), "r"(b1))

// ---------------- K_prep: W -> fp16, zero den+out, batch dtype flag -------
__global__ void k_prep(const float* __restrict__ W,
                       const void* __restrict__ bt, int V,
                       float* __restrict__ out, int out_n) {
    int i = blockIdx.x * 256 + threadIdx.x;
    if (i < out_n) out[i] = 0.f;
    if (i < HS * D) g_Wh[i] = __float2half_rn(W[i]);
    if (i < MAXG) g_den[i] = 0.f;
    if (i == 0)
        g_is64 = (((const unsigned long long*)bt)[V / 2 - 1] < (1ULL << 31)) ? 1 : 0;
}

// ---------------- staging: TILE x 128 fp32 -> fp16 (packed cvt) -----------
__device__ __forceinline__ void stage_tile(char* smem, const float* __restrict__ H,
                                           long tile, int buf, int V,
                                           int tpart, int npart) {
    __half* dst = (__half*)(smem + SM_ABUF + buf * ABUF_SZ);
    for (int idx = tpart; idx < TILE * 16; idx += npart) {
        int row = idx >> 4;
        int k8  = (idx & 15) << 3;
        long gr = tile * TILE + row;
        float4 v0 = make_float4(0.f, 0.f, 0.f, 0.f), v1 = v0;
        if (gr < (long)V) {
            const float4* p = (const float4*)(H + (size_t)gr * D + k8);
            v0 = p[0];
            v1 = p[1];
        }
        __half2 h0 = __float22half2_rn(make_float2(v0.x, v0.y));
        __half2 h1 = __float22half2_rn(make_float2(v0.z, v0.w));
        __half2 h2 = __float22half2_rn(make_float2(v1.x, v1.y));
        __half2 h3 = __float22half2_rn(make_float2(v1.z, v1.w));
        uint4 pack = make_uint4(*(unsigned*)&h0, *(unsigned*)&h1,
                                *(unsigned*)&h2, *(unsigned*)&h3);
        *(uint4*)(dst + row * AP + k8) = pack;
    }
}

__device__ __forceinline__ void stage_bat(char* smem, const void* __restrict__ bt,
                                          long tile, int slot, int V, int is64,
                                          int tpart) {
    int* dst = (int*)(smem + SM_SBAT + slot * 512);
    long gr = tile * TILE + tpart;
    int g = -1;
    if (gr < (long)V)
        g = is64 ? (int)((const long long*)bt)[gr] : ((const int*)bt)[gr];
    dst[tpart] = g;
}

// ---------------- K1: pipelined fp16 HMMA + producer-side softmax-pool ----
__global__ __launch_bounds__(NTHR, 1) void k1_tc(const float* __restrict__ H,
                                                 const void* __restrict__ bt,
                                                 const float* __restrict__ bp,
                                                 const float* __restrict__ ws,
                                                 float* __restrict__ num,
                                                 int V, int nTiles) {
    extern __shared__ __align__(16) char smem[];
    int tid = threadIdx.x, wid = tid >> 5, lane = tid & 31;
    float* sb    = (float*)(smem + SM_SB);
    float* sw    = (float*)(smem + SM_SW);
    float* spool = (float*)(smem + SM_POOL);  // [128]

    if (tid < 128) { sb[tid] = bp[tid]; sw[tid] = ws[tid]; }
    int is64 = g_is64;

    // stage stationary B = fp16(W)
    for (int idx = tid; idx < 128 * 16; idx += NTHR) {
        int row = idx >> 4;
        int k8  = (idx & 15) << 3;
        uint4 vh = *(const uint4*)(g_Wh + row * D + k8);
        *(uint4*)((__half*)(smem + SM_BHI) + row * AP + k8) = vh;
    }

    int nt = 0;
    {
        int rem = nTiles - blockIdx.x;
        if (rem > 0) nt = (rem + (int)gridDim.x - 1) / (int)gridDim.x;
    }

    // prologue: stage tiles 0 and 1 (all threads)
    if (nt > 0) {
        stage_tile((char*)smem, H, (long)blockIdx.x, 0, V, tid, NTHR);
        if (tid < 128)
            stage_bat((char*)smem, bt, (long)blockIdx.x, 0, V, is64, tid);
    }
    if (nt > 1) {
        long t1 = (long)blockIdx.x + gridDim.x;
        stage_tile((char*)smem, H, t1, 1, V, tid, NTHR);
        if (tid >= 128 && tid < 256)
            stage_bat((char*)smem, bt, t1, 1, V, is64, tid - 128);
    }
    __syncthreads();

    // consumer geometry (warps 0-7): 4(M) x 2(N), warp tile 32 x 64
    int wm = wid >> 1, wn = wid & 1;
    int rb = wm * 32, cb = wn * 64;
    unsigned aoff = ((rb + (lane & 15)) * AP + ((lane >> 4) << 3)) * 2;
    unsigned boff =
        ((cb + (lane & 7) + ((lane >> 4) << 3)) * AP + (((lane >> 3) & 1) << 3)) * 2;
    unsigned bhi_s = su32(smem + SM_BHI) + boff;

    // consumer epilogue constants
    float bv[16], wv[16];
    if (wid < 8) {
#pragma unroll
        for (int q = 0; q < 8; ++q)
#pragma unroll
            for (int par = 0; par < 2; ++par) {
                int col = cb + q * 8 + (lane & 3) * 2 + par;
                bv[q * 2 + par] = sb[col];
                wv[q * 2 + par] = sw[col];
            }
    }

    for (int j = 0; j <= nt; ++j) {
        if (wid < 8) {
            if (j < nt) {
                int ab = j & 3;
                unsigned a_s = su32(smem + SM_ABUF + ab * ABUF_SZ) + aoff;

                float acc[2][8][4];
#pragma unroll
                for (int s = 0; s < 2; s++)
#pragma unroll
                    for (int q = 0; q < 8; q++)
#pragma unroll
                        for (int c = 0; c < 4; c++) acc[s][q][c] = 0.f;

#pragma unroll
                for (int kk = 0; kk < 8; ++kk) {
                    unsigned ah[2][4], bh[16];
#pragma unroll
                    for (int s = 0; s < 2; ++s)
                        LDSM4(ah[s][0], ah[s][1], ah[s][2], ah[s][3],
                              a_s + kk * 32 + s * (16 * AP * 2));
#pragma unroll
                    for (int p = 0; p < 4; ++p)
                        LDSM4(bh[4 * p], bh[4 * p + 1], bh[4 * p + 2],
                              bh[4 * p + 3],
                              bhi_s + kk * 32 + p * (16 * AP * 2));
#pragma unroll
                    for (int s = 0; s < 2; ++s)
#pragma unroll
                        for (int q = 0; q < 8; ++q) {
                            int bi = (q >> 1) * 4 + ((q & 1) << 1);
                            MMA16816F(acc[s][q], ah[s][0], ah[s][1], ah[s][2],
                                      ah[s][3], bh[bi], bh[bi + 1]);
                        }
                }

                // tanh-dot -> se[j&1] (partial per wn; producers combine)
                float ps[4] = {0.f, 0.f, 0.f, 0.f};
#pragma unroll
                for (int s = 0; s < 2; ++s)
#pragma unroll
                    for (int q = 0; q < 8; ++q)
#pragma unroll
                        for (int e = 0; e < 4; ++e) {
                            float z = acc[s][q][e] + bv[q * 2 + (e & 1)];
                            ps[s * 2 + (e >> 1)] +=
                                tanh_approx(z) * wv[q * 2 + (e & 1)];
                        }
#pragma unroll
                for (int q = 0; q < 4; ++q) {
                    ps[q] += __shfl_xor_sync(0xffffffffu, ps[q], 1);
                    ps[q] += __shfl_xor_sync(0xffffffffu, ps[q], 2);
                }
                if ((lane & 3) == 0) {
                    float* seW = (float*)(smem + SM_SE + (j & 1) * 1024);
#pragma unroll
                    for (int q = 0; q < 4; ++q) {
                        int r = rb + (q >> 1) * 16 + (lane >> 2) + (q & 1) * 8;
                        seW[wn * 128 + r] = ps[q];
                    }
                }
            }
        } else {
            int ptid = tid - 256;  // [0,128)
            // stage tile j+2
            if (j + 2 < nt) {
                long tj2 = (long)blockIdx.x + (long)(j + 2) * gridDim.x;
                stage_tile((char*)smem, H, tj2, (j + 2) & 3, V, ptid, 128);
                stage_bat((char*)smem, bt, tj2, (j + 2) & 3, V, is64, ptid);
            }
            // softmax-pool tile j-1
            if (j >= 1) {
                int jb = (j - 1) & 3;
                long tjm = (long)blockIdx.x + (long)(j - 1) * gridDim.x;
                const float* seR = (const float*)(smem + SM_SE + ((j - 1) & 1) * 1024);
                const int* sbat = (const int*)(smem + SM_SBAT + jb * 512);
                {
                    long grow = tjm * TILE + ptid;
                    float e = seR[ptid] + seR[128 + ptid];
                    spool[ptid] = (grow < (long)V) ? __expf(e) : 0.f;
                }
                asm volatile("bar.sync 2, 128;" ::: "memory");

                const __half* hh = (const __half*)(smem + SM_ABUF + jb * ABUF_SZ);
                int pw = ptid >> 5;
                int r0 = pw * 32;
                int d4 = lane * 4;
                float pacc0 = 0.f, pacc1 = 0.f, pacc2 = 0.f, pacc3 = 0.f;
                float psum = 0.f;
                int g = sbat[r0];
#pragma unroll
                for (int rr = 0; rr < 32; ++rr) {
                    int r = r0 + rr;
                    int gr = sbat[r];
                    if (gr != g) {
                        if (g >= 0) {
                            float* dst = num + (size_t)g * D + d4;
                            atomicAdd(dst + 0, pacc0);
                            atomicAdd(dst + 1, pacc1);
                            atomicAdd(dst + 2, pacc2);
                            atomicAdd(dst + 3, pacc3);
                            if (lane == 0) atomicAdd(g_den + g, psum);
                        }
                        pacc0 = pacc1 = pacc2 = pacc3 = 0.f;
                        psum = 0.f;
                        g = gr;
                    }
                    float p = spool[r];
                    uint2 vh = *(const uint2*)(hh + r * AP + d4);
                    __half2 h0 = *(__half2*)&vh.x, h1 = *(__half2*)&vh.y;
                    float2 f0 = __half22float2(h0), f1 = __half22float2(h1);
                    pacc0 += p * f0.x;
                    pacc1 += p * f0.y;
                    pacc2 += p * f1.x;
                    pacc3 += p * f1.y;
                    psum += p;
                }
                if (g >= 0) {
                    float* dst = num + (size_t)g * D + d4;
                    atomicAdd(dst + 0, pacc0);
                    atomicAdd(dst + 1, pacc1);
                    atomicAdd(dst + 2, pacc2);
                    atomicAdd(dst + 3, pacc3);
                    if (lane == 0) atomicAdd(g_den + g, psum);
                }
            }
        }
        __syncthreads();
    }
}

// ---------------- K_div: out = num / max(den, 1e-12) ----------------
__global__ void k_div(float* __restrict__ out, int n) {
    int i = blockIdx.x * 256 + threadIdx.x;
    if (i < n) out[i] = out[i] / fmaxf(g_den[i >> 7], 1e-12f);
}

// ---------------- launch ----------------
extern "C" void kernel_launch(void* const* d_in, const int* in_sizes, int n_in,
                              void* d_out, int out_size) {
    const float* H  = (const float*)d_in[0];
    const void*  bt = d_in[1];
    const float* Wp = (const float*)d_in[2];
    const float* bp = (const float*)d_in[3];
    const float* ws = (const float*)d_in[4];
    float* out = (float*)d_out;

    int V = in_sizes[1];
    int nTiles = (V + TILE - 1) / TILE;

    cudaFuncSetAttribute(k1_tc, cudaFuncAttributeMaxDynamicSharedMemorySize,
                         SMEM1_TOTAL);

    k_prep<<<(out_size + 255) / 256, 256>>>(Wp, bt, V, out, out_size);
    k1_tc<<<NSM, NTHR, SMEM1_TOTAL>>>(H, bt, bp, ws, out, V, nTiles);
    k_div<<<(out_size + 255) / 256, 256>>>(out, out_size);
}

// round 11
// speedup vs baseline: 1.3997x; 1.3997x over previous
#include <cuda_runtime.h>
#include <cuda_fp16.h>
#include <cstdint>

#define D    128
#define HS   128
#define MAXG 16384
#define AP   136      // padded smem row pitch in fp16 elems
#define TILE 64       // rows per tile (2 CTAs per SM)
#define NCTA 296
#define NTHR 192      // 4 consumer warps + 2 producer warps

// ---------------- device scratch ----------------
__device__ float g_den[MAXG];
__device__ int   g_is64;
__device__ __align__(16) __half g_Wh[HS * D];

// ---------------- smem layout (bytes) ----------------
#define SM_SB    0                       // 128 f32 bias
#define SM_SW    512                     // 128 f32 w_score
#define SM_SE    1024                    // 2 x 64 f32 = 512
#define SM_POOL  1536                    // 64 f32 exp(e)
#define SM_BAT0  1792                    // 64 int batch ids (buf 0)
#define SM_BAT1  2048                    // 64 int batch ids (buf 1)
#define SM_BHI   2304                    // 128 x AP fp16 = 34816
#define SM_A0    (SM_BHI + 34816)        // 37120  (64 x AP fp16 = 17408)
#define SM_A1    (SM_A0 + 17408)         // 54528
#define SMEM1_TOTAL (SM_A1 + 17408)      // 71936

// ---------------- helpers ----------------
__device__ __forceinline__ unsigned su32(const void* p) {
    return (unsigned)__cvta_generic_to_shared(p);
}
__device__ __forceinline__ float tanh_approx(float x) {
    float y;
    asm("tanh.approx.f32 %0, %1;" : "=f"(y) : "f"(x));
    return y;
}

#define LDSM4(r0, r1, r2, r3, addr)                                          \
    asm volatile("ldmatrix.sync.aligned.m8n8.x4.shared.b16 {%0,%1,%2,%3}, [%4];" \
                 : "=r"(r0), "=r"(r1), "=r"(r2), "=r"(r3) : "r"(addr))

#define MMA16816F(c, a0, a1, a2, a3, b0, b1)                                 \
    asm volatile(                                                            \
        "mma.sync.aligned.m16n8k16.row.col.f32.f16.f16.f32 "                 \
        "{%0,%1,%2,%3},{%4,%5,%6,%7},{%8,%9},{%0,%1,%2,%3};"                 \
        : "+f"(c[0]), "+f"(c[1]), "+f"(c[2]), "+f"(c[3])                     \
        : "r"(a0), "r"(a1), "r"(a2), "r"(a3), "r"(b0), "r"(b1))

// ---------------- K_prep: W -> fp16, zero den+out, batch dtype flag -------
__global__ void k_prep(const float* __restrict__ W,
                       const void* __restrict__ bt, int V,
                       float* __restrict__ out, int out_n) {
    int i = blockIdx.x * 256 + threadIdx.x;
    if (i < out_n) out[i] = 0.f;
    if (i < HS * D) g_Wh[i] = __float2half_rn(W[i]);
    if (i < MAXG) g_den[i] = 0.f;
    if (i == 0)
        g_is64 = (((const unsigned long long*)bt)[V / 2 - 1] < (1ULL << 31)) ? 1 : 0;
}

// ---------------- staging: TILE x 128 fp32 -> fp16 (packed cvt) -----------
__device__ __forceinline__ void stage_tile(char* smem, const float* __restrict__ H,
                                           long tile, int buf, int V,
                                           int tpart, int npart) {
    __half* dst = (__half*)(smem + (buf ? SM_A1 : SM_A0));
    for (int idx = tpart; idx < TILE * 16; idx += npart) {
        int row = idx >> 4;
        int k8  = (idx & 15) << 3;
        long gr = tile * TILE + row;
        float4 v0 = make_float4(0.f, 0.f, 0.f, 0.f), v1 = v0;
        if (gr < (long)V) {
            const float4* p = (const float4*)(H + (size_t)gr * D + k8);
            v0 = p[0];
            v1 = p[1];
        }
        __half2 h0 = __float22half2_rn(make_float2(v0.x, v0.y));
        __half2 h1 = __float22half2_rn(make_float2(v0.z, v0.w));
        __half2 h2 = __float22half2_rn(make_float2(v1.x, v1.y));
        __half2 h3 = __float22half2_rn(make_float2(v1.z, v1.w));
        uint4 pack = make_uint4(*(unsigned*)&h0, *(unsigned*)&h1,
                                *(unsigned*)&h2, *(unsigned*)&h3);
        *(uint4*)(dst + row * AP + k8) = pack;
    }
}

__device__ __forceinline__ void stage_bat(char* smem, const void* __restrict__ bt,
                                          long tile, int buf, int V, int is64,
                                          int tpart) {
    // tpart in [0,TILE)
    int* dst = (int*)(smem + (buf ? SM_BAT1 : SM_BAT0));
    long gr = tile * TILE + tpart;
    int g = -1;
    if (gr < (long)V)
        g = is64 ? (int)((const long long*)bt)[gr] : ((const int*)bt)[gr];
    dst[tpart] = g;
}

// ---------------- K1: persistent fp16 HMMA + fused softmax-pool -----------
// 2 CTAs per SM: epilogue of one CTA overlaps MMA of the other.
__global__ __launch_bounds__(NTHR, 2) void k1_tc(const float* __restrict__ H,
                                                 const void* __restrict__ bt,
                                                 const float* __restrict__ bp,
                                                 const float* __restrict__ ws,
                                                 float* __restrict__ num,
                                                 int V, int nTiles) {
    extern __shared__ __align__(16) char smem[];
    int tid = threadIdx.x, wid = tid >> 5, lane = tid & 31;
    float* sb    = (float*)(smem + SM_SB);
    float* sw    = (float*)(smem + SM_SW);
    float* se    = (float*)(smem + SM_SE);    // [2][64]
    float* spool = (float*)(smem + SM_POOL);  // [64]

    if (tid < 128) { sb[tid] = bp[tid]; sw[tid] = ws[tid]; }
    int is64 = g_is64;

    // stage stationary B = fp16(W)
    for (int idx = tid; idx < 128 * 16; idx += NTHR) {
        int row = idx >> 4;
        int k8  = (idx & 15) << 3;
        uint4 vh = *(const uint4*)(g_Wh + row * D + k8);
        *(uint4*)((__half*)(smem + SM_BHI) + row * AP + k8) = vh;
    }

    int nt = 0;
    {
        int rem = nTiles - blockIdx.x;
        if (rem > 0) nt = (rem + (int)gridDim.x - 1) / (int)gridDim.x;
    }

    if (nt > 0) {
        stage_tile((char*)smem, H, (long)blockIdx.x, 0, V, tid, NTHR);
        if (tid < TILE)
            stage_bat((char*)smem, bt, (long)blockIdx.x, 0, V, is64, tid);
    }
    __syncthreads();

    // consumer geometry (warps 0-3): 2(M) x 2(N), warp tile 32 x 64
    int wm = wid >> 1, wn = wid & 1;
    int rb = wm * 32, cb = wn * 64;
    unsigned aoff = ((rb + (lane & 15)) * AP + ((lane >> 4) << 3)) * 2;
    unsigned boff =
        ((cb + (lane & 7) + ((lane >> 4) << 3)) * AP + (((lane >> 3) & 1) << 3)) * 2;
    unsigned bhi_s = su32(smem + SM_BHI) + boff;

    // consumer epilogue constants
    float bv[16], wv[16];
    if (wid < 4) {
#pragma unroll
        for (int q = 0; q < 8; ++q)
#pragma unroll
            for (int par = 0; par < 2; ++par) {
                int col = cb + q * 8 + (lane & 3) * 2 + par;
                bv[q * 2 + par] = sb[col];
                wv[q * 2 + par] = sw[col];
            }
    }

    for (int j = 0; j < nt; ++j) {
        int b = j & 1, bn = (j + 1) & 1;
        long tj = (long)blockIdx.x + (long)j * gridDim.x;
        int* sbat = (int*)(smem + (b ? SM_BAT1 : SM_BAT0));

        if (wid >= 4) {
            // producers (2 warps): stage next tile + next batch ids
            if (j + 1 < nt) {
                long tj1 = (long)blockIdx.x + (long)(j + 1) * gridDim.x;
                stage_tile((char*)smem, H, tj1, bn, V, tid - 128, 64);
                if (tid - 128 < TILE)
                    stage_bat((char*)smem, bt, tj1, bn, V, is64, tid - 128);
            }
        } else {
            unsigned a_s = su32(smem + (b ? SM_A1 : SM_A0)) + aoff;

            float acc[2][8][4];
#pragma unroll
            for (int s = 0; s < 2; s++)
#pragma unroll
                for (int q = 0; q < 8; q++)
#pragma unroll
                    for (int c = 0; c < 4; c++) acc[s][q][c] = 0.f;

#pragma unroll
            for (int kk = 0; kk < 8; ++kk) {
                unsigned ah[2][4], bh[16];
#pragma unroll
                for (int s = 0; s < 2; ++s)
                    LDSM4(ah[s][0], ah[s][1], ah[s][2], ah[s][3],
                          a_s + kk * 32 + s * (16 * AP * 2));
#pragma unroll
                for (int p = 0; p < 4; ++p)
                    LDSM4(bh[4 * p], bh[4 * p + 1], bh[4 * p + 2], bh[4 * p + 3],
                          bhi_s + kk * 32 + p * (16 * AP * 2));
#pragma unroll
                for (int s = 0; s < 2; ++s)
#pragma unroll
                    for (int q = 0; q < 8; ++q) {
                        int bi = (q >> 1) * 4 + ((q & 1) << 1);
                        MMA16816F(acc[s][q], ah[s][0], ah[s][1], ah[s][2],
                                  ah[s][3], bh[bi], bh[bi + 1]);
                    }
            }

            // epilogue part 1: tanh-dot -> se
            float ps[4] = {0.f, 0.f, 0.f, 0.f};
#pragma unroll
            for (int s = 0; s < 2; ++s)
#pragma unroll
                for (int q = 0; q < 8; ++q)
#pragma unroll
                    for (int e = 0; e < 4; ++e) {
                        float z = acc[s][q][e] + bv[q * 2 + (e & 1)];
                        ps[s * 2 + (e >> 1)] += tanh_approx(z) * wv[q * 2 + (e & 1)];
                    }
#pragma unroll
            for (int q = 0; q < 4; ++q) {
                ps[q] += __shfl_xor_sync(0xffffffffu, ps[q], 1);
                ps[q] += __shfl_xor_sync(0xffffffffu, ps[q], 2);
            }
            if ((lane & 3) == 0) {
#pragma unroll
                for (int q = 0; q < 4; ++q) {
                    int r = rb + (q >> 1) * 16 + (lane >> 2) + (q & 1) * 8;
                    se[wn * 64 + r] = ps[q];
                }
            }
            asm volatile("bar.sync 1, 128;" ::: "memory");

            // epilogue part 2: p = exp(e) (no max shift: |e| <= ||w||_1 ~ 9)
            if (tid < TILE) {
                long grow = tj * TILE + tid;
                float e = se[tid] + se[64 + tid];
                spool[tid] = (grow < (long)V) ? __expf(e) : 0.f;
            }
            asm volatile("bar.sync 1, 128;" ::: "memory");

            // epilogue part 3: parallel segment pooling from fp16 H tile.
            // Warp w owns rows [16w, 16w+16); lane owns 4 d-cols.
            {
                const __half* hh = (const __half*)(smem + (b ? SM_A1 : SM_A0));
                int r0 = wid * 16;
                int d4 = lane * 4;
                float pacc0 = 0.f, pacc1 = 0.f, pacc2 = 0.f, pacc3 = 0.f;
                float psum = 0.f;
                int g = sbat[r0];
#pragma unroll
                for (int rr = 0; rr < 16; ++rr) {
                    int r = r0 + rr;
                    int gr = sbat[r];
                    if (gr != g) {
                        if (g >= 0) {
                            float* dst = num + (size_t)g * D + d4;
                            atomicAdd(dst + 0, pacc0);
                            atomicAdd(dst + 1, pacc1);
                            atomicAdd(dst + 2, pacc2);
                            atomicAdd(dst + 3, pacc3);
                            if (lane == 0) atomicAdd(g_den + g, psum);
                        }
                        pacc0 = pacc1 = pacc2 = pacc3 = 0.f;
                        psum = 0.f;
                        g = gr;
                    }
                    float p = spool[r];
                    uint2 vh = *(const uint2*)(hh + r * AP + d4);
                    __half2 h0 = *(__half2*)&vh.x, h1 = *(__half2*)&vh.y;
                    float2 f0 = __half22float2(h0), f1 = __half22float2(h1);
                    pacc0 += p * f0.x;
                    pacc1 += p * f0.y;
                    pacc2 += p * f1.x;
                    pacc3 += p * f1.y;
                    psum += p;
                }
                if (g >= 0) {
                    float* dst = num + (size_t)g * D + d4;
                    atomicAdd(dst + 0, pacc0);
                    atomicAdd(dst + 1, pacc1);
                    atomicAdd(dst + 2, pacc2);
                    atomicAdd(dst + 3, pacc3);
                    if (lane == 0) atomicAdd(g_den + g, psum);
                }
            }
        }
        __syncthreads();
    }
}

// ---------------- K_div: out = num / max(den, 1e-12) ----------------
__global__ void k_div(float* __restrict__ out, int n) {
    int i = blockIdx.x * 256 + threadIdx.x;
    if (i < n) out[i] = out[i] / fmaxf(g_den[i >> 7], 1e-12f);
}

// ---------------- launch ----------------
extern "C" void kernel_launch(void* const* d_in, const int* in_sizes, int n_in,
                              void* d_out, int out_size) {
    const float* H  = (const float*)d_in[0];
    const void*  bt = d_in[1];
    const float* Wp = (const float*)d_in[2];
    const float* bp = (const float*)d_in[3];
    const float* ws = (const float*)d_in[4];
    float* out = (float*)d_out;

    int V = in_sizes[1];
    int nTiles = (V + TILE - 1) / TILE;

    cudaFuncSetAttribute(k1_tc, cudaFuncAttributeMaxDynamicSharedMemorySize,
                         SMEM1_TOTAL);

    k_prep<<<(out_size + 255) / 256, 256>>>(Wp, bt, V, out, out_size);
    k1_tc<<<NCTA, NTHR, SMEM1_TOTAL>>>(H, bt, bp, ws, out, V, nTiles);
    k_div<<<(out_size + 255) / 256, 256>>>(out, out_size);
}

// round 12
// speedup vs baseline: 1.6038x; 1.1458x over previous
#include <cuda_runtime.h>
#include <cuda_fp16.h>
#include <cstdint>

#define D    128
#define HS   128
#define MAXG 16384
#define AP   136      // padded smem row pitch in fp16 elems
#define TILE 64       // rows per tile (3 CTAs per SM)
#define NCTA 444
#define NTHR 192      // 4 consumer warps + 2 producer warps

// ---------------- device scratch ----------------
__device__ float g_den[MAXG];
__device__ int   g_is64;
__device__ __align__(16) __half g_Wh[HS * D];

// ---------------- smem layout (bytes) ----------------
#define SM_BW    0                       // 128 half2 (bias, w) = 512
#define SM_SE    512                     // 2 x 64 f32 = 512
#define SM_BAT0  1024                    // 64 int = 256
#define SM_BAT1  1280                    // 64 int = 256
#define SM_BHI   1536                    // 128 x AP fp16 = 34816
#define SM_A0    (SM_BHI + 34816)        // 36352  (64 x AP fp16 = 17408)
#define SM_A1    (SM_A0 + 17408)         // 53760
#define SMEM1_TOTAL (SM_A1 + 17408)      // 71168  (x3 = 213504 <= 228KB)

// ---------------- helpers ----------------
__device__ __forceinline__ unsigned su32(const void* p) {
    return (unsigned)__cvta_generic_to_shared(p);
}
__device__ __forceinline__ float tanh_approx(float x) {
    float y;
    asm("tanh.approx.f32 %0, %1;" : "=f"(y) : "f"(x));
    return y;
}

#define LDSM4(r0, r1, r2, r3, addr)                                          \
    asm volatile("ldmatrix.sync.aligned.m8n8.x4.shared.b16 {%0,%1,%2,%3}, [%4];" \
                 : "=r"(r0), "=r"(r1), "=r"(r2), "=r"(r3) : "r"(addr))

#define MMA16816F(c, a0, a1, a2, a3, b0, b1)                                 \
    asm volatile(                                                            \
        "mma.sync.aligned.m16n8k16.row.col.f32.f16.f16.f32 "                 \
        "{%0,%1,%2,%3},{%4,%5,%6,%7},{%8,%9},{%0,%1,%2,%3};"                 \
        : "+f"(c[0]), "+f"(c[1]), "+f"(c[2]), "+f"(c[3])                     \
        : "r"(a0), "r"(a1), "r"(a2), "r"(a3), "r"(b0), "r"(b1))

// ---------------- K_prep: W -> fp16, zero den+out, batch dtype flag -------
__global__ void k_prep(const float* __restrict__ W,
                       const void* __restrict__ bt, int V,
                       float* __restrict__ out, int out_n) {
    int i = blockIdx.x * 256 + threadIdx.x;
    if (i < out_n) out[i] = 0.f;
    if (i < HS * D) g_Wh[i] = __float2half_rn(W[i]);
    if (i < MAXG) g_den[i] = 0.f;
    if (i == 0)
        g_is64 = (((const unsigned long long*)bt)[V / 2 - 1] < (1ULL << 31)) ? 1 : 0;
}

// ---------------- staging: TILE x 128 fp32 -> fp16 (packed cvt) -----------
__device__ __forceinline__ void stage_tile(char* smem, const float* __restrict__ H,
                                           long tile, int buf, int V,
                                           int tpart, int npart) {
    __half* dst = (__half*)(smem + (buf ? SM_A1 : SM_A0));
    for (int idx = tpart; idx < TILE * 16; idx += npart) {
        int row = idx >> 4;
        int k8  = (idx & 15) << 3;
        long gr = tile * TILE + row;
        float4 v0 = make_float4(0.f, 0.f, 0.f, 0.f), v1 = v0;
        if (gr < (long)V) {
            const float4* p = (const float4*)(H + (size_t)gr * D + k8);
            v0 = p[0];
            v1 = p[1];
        }
        __half2 h0 = __float22half2_rn(make_float2(v0.x, v0.y));
        __half2 h1 = __float22half2_rn(make_float2(v0.z, v0.w));
        __half2 h2 = __float22half2_rn(make_float2(v1.x, v1.y));
        __half2 h3 = __float22half2_rn(make_float2(v1.z, v1.w));
        uint4 pack = make_uint4(*(unsigned*)&h0, *(unsigned*)&h1,
                                *(unsigned*)&h2, *(unsigned*)&h3);
        *(uint4*)(dst + row * AP + k8) = pack;
    }
}

__device__ __forceinline__ void stage_bat(char* smem, const void* __restrict__ bt,
                                          long tile, int buf, int V, int is64,
                                          int tpart) {
    // tpart in [0,TILE)
    int* dst = (int*)(smem + (buf ? SM_BAT1 : SM_BAT0));
    long gr = tile * TILE + tpart;
    int g = -1;
    if (gr < (long)V)
        g = is64 ? (int)((const long long*)bt)[gr] : ((const int*)bt)[gr];
    dst[tpart] = g;
}

// ---------------- K1: persistent fp16 HMMA + fused softmax-pool -----------
// 3 CTAs per SM: epilogues overlap other CTAs' MMA phases.
__global__ __launch_bounds__(NTHR, 3) void k1_tc(const float* __restrict__ H,
                                                 const void* __restrict__ bt,
                                                 const float* __restrict__ bp,
                                                 const float* __restrict__ ws,
                                                 float* __restrict__ num,
                                                 int V, int nTiles) {
    extern __shared__ __align__(16) char smem[];
    int tid = threadIdx.x, wid = tid >> 5, lane = tid & 31;
    __half2* bw = (__half2*)(smem + SM_BW);   // (bias, w) per col
    float* se   = (float*)(smem + SM_SE);     // [2][64]

    if (tid < 128)
        bw[tid] = __floats2half2_rn(bp[tid], ws[tid]);
    int is64 = g_is64;

    // stage stationary B = fp16(W)
    for (int idx = tid; idx < 128 * 16; idx += NTHR) {
        int row = idx >> 4;
        int k8  = (idx & 15) << 3;
        uint4 vh = *(const uint4*)(g_Wh + row * D + k8);
        *(uint4*)((__half*)(smem + SM_BHI) + row * AP + k8) = vh;
    }

    int nt = 0;
    {
        int rem = nTiles - blockIdx.x;
        if (rem > 0) nt = (rem + (int)gridDim.x - 1) / (int)gridDim.x;
    }

    if (nt > 0) {
        stage_tile((char*)smem, H, (long)blockIdx.x, 0, V, tid, NTHR);
        if (tid < TILE)
            stage_bat((char*)smem, bt, (long)blockIdx.x, 0, V, is64, tid);
    }
    __syncthreads();

    // consumer geometry (warps 0-3): 2(M) x 2(N), warp tile 32 x 64
    int wm = wid >> 1, wn = wid & 1;
    int rb = wm * 32, cb = wn * 64;
    unsigned aoff = ((rb + (lane & 15)) * AP + ((lane >> 4) << 3)) * 2;
    unsigned boff =
        ((cb + (lane & 7) + ((lane >> 4) << 3)) * AP + (((lane >> 3) & 1) << 3)) * 2;
    unsigned bhi_s = su32(smem + SM_BHI) + boff;

    // consumer epilogue constants: packed (b, w) per owned column
    unsigned hw[16];
    if (wid < 4) {
#pragma unroll
        for (int q = 0; q < 8; ++q)
#pragma unroll
            for (int par = 0; par < 2; ++par) {
                int col = cb + q * 8 + (lane & 3) * 2 + par;
                hw[q * 2 + par] = *(unsigned*)&bw[col];
            }
    }

    for (int j = 0; j < nt; ++j) {
        int b = j & 1, bn = (j + 1) & 1;
        long tj = (long)blockIdx.x + (long)j * gridDim.x;
        int* sbat = (int*)(smem + (b ? SM_BAT1 : SM_BAT0));

        if (wid >= 4) {
            // producers (2 warps): stage next tile + next batch ids
            if (j + 1 < nt) {
                long tj1 = (long)blockIdx.x + (long)(j + 1) * gridDim.x;
                stage_tile((char*)smem, H, tj1, bn, V, tid - 128, 64);
                if (tid - 128 < TILE)
                    stage_bat((char*)smem, bt, tj1, bn, V, is64, tid - 128);
            }
        } else {
            unsigned a_s = su32(smem + (b ? SM_A1 : SM_A0)) + aoff;

            float acc[2][8][4];
#pragma unroll
            for (int s = 0; s < 2; s++)
#pragma unroll
                for (int q = 0; q < 8; q++)
#pragma unroll
                    for (int c = 0; c < 4; c++) acc[s][q][c] = 0.f;

#pragma unroll
            for (int kk = 0; kk < 8; ++kk) {
                unsigned ah[2][4], bh[16];
#pragma unroll
                for (int s = 0; s < 2; ++s)
                    LDSM4(ah[s][0], ah[s][1], ah[s][2], ah[s][3],
                          a_s + kk * 32 + s * (16 * AP * 2));
#pragma unroll
                for (int p = 0; p < 4; ++p)
                    LDSM4(bh[4 * p], bh[4 * p + 1], bh[4 * p + 2], bh[4 * p + 3],
                          bhi_s + kk * 32 + p * (16 * AP * 2));
#pragma unroll
                for (int s = 0; s < 2; ++s)
#pragma unroll
                    for (int q = 0; q < 8; ++q) {
                        int bi = (q >> 1) * 4 + ((q & 1) << 1);
                        MMA16816F(acc[s][q], ah[s][0], ah[s][1], ah[s][2],
                                  ah[s][3], bh[bi], bh[bi + 1]);
                    }
            }

            // epilogue part 1: tanh-dot -> se
            float ps[4] = {0.f, 0.f, 0.f, 0.f};
#pragma unroll
            for (int s = 0; s < 2; ++s)
#pragma unroll
                for (int q = 0; q < 8; ++q)
#pragma unroll
                    for (int e = 0; e < 4; ++e) {
                        __half2 hv = *(__half2*)&hw[q * 2 + (e & 1)];
                        float2 bwf = __half22float2(hv);
                        float z = acc[s][q][e] + bwf.x;
                        ps[s * 2 + (e >> 1)] += tanh_approx(z) * bwf.y;
                    }
#pragma unroll
            for (int q = 0; q < 4; ++q) {
                ps[q] += __shfl_xor_sync(0xffffffffu, ps[q], 1);
                ps[q] += __shfl_xor_sync(0xffffffffu, ps[q], 2);
            }
            if ((lane & 3) == 0) {
#pragma unroll
                for (int q = 0; q < 4; ++q) {
                    int r = rb + (q >> 1) * 16 + (lane >> 2) + (q & 1) * 8;
                    se[wn * 64 + r] = ps[q];
                }
            }
            asm volatile("bar.sync 1, 128;" ::: "memory");

            // epilogue part 2: pooling with inline exp (no max shift needed:
            // |e| <= ||w||_1 ~ 9). Warp w owns rows [16w,16w+16); lane: 4 cols.
            {
                const __half* hh = (const __half*)(smem + (b ? SM_A1 : SM_A0));
                int r0 = wid * 16;
                int d4 = lane * 4;
                float pacc0 = 0.f, pacc1 = 0.f, pacc2 = 0.f, pacc3 = 0.f;
                float psum = 0.f;
                int g = sbat[r0];
#pragma unroll
                for (int rr = 0; rr < 16; ++rr) {
                    int r = r0 + rr;
                    int gr = sbat[r];
                    if (gr != g) {
                        if (g >= 0) {
                            float* dst = num + (size_t)g * D + d4;
                            atomicAdd(dst + 0, pacc0);
                            atomicAdd(dst + 1, pacc1);
                            atomicAdd(dst + 2, pacc2);
                            atomicAdd(dst + 3, pacc3);
                            if (lane == 0) atomicAdd(g_den + g, psum);
                        }
                        pacc0 = pacc1 = pacc2 = pacc3 = 0.f;
                        psum = 0.f;
                        g = gr;
                    }
                    float p = __expf(se[r] + se[64 + r]);
                    uint2 vh = *(const uint2*)(hh + r * AP + d4);
                    __half2 h0 = *(__half2*)&vh.x, h1 = *(__half2*)&vh.y;
                    float2 f0 = __half22float2(h0), f1 = __half22float2(h1);
                    pacc0 += p * f0.x;
                    pacc1 += p * f0.y;
                    pacc2 += p * f1.x;
                    pacc3 += p * f1.y;
                    psum += p;
                }
                if (g >= 0) {
                    float* dst = num + (size_t)g * D + d4;
                    atomicAdd(dst + 0, pacc0);
                    atomicAdd(dst + 1, pacc1);
                    atomicAdd(dst + 2, pacc2);
                    atomicAdd(dst + 3, pacc3);
                    if (lane == 0) atomicAdd(g_den + g, psum);
                }
            }
        }
        __syncthreads();
    }
}

// ---------------- K_div: out = num / max(den, 1e-12) ----------------
__global__ void k_div(float* __restrict__ out, int n) {
    int i = blockIdx.x * 256 + threadIdx.x;
    if (i < n) out[i] = out[i] / fmaxf(g_den[i >> 7], 1e-12f);
}

// ---------------- launch ----------------
extern "C" void kernel_launch(void* const* d_in, const int* in_sizes, int n_in,
                              void* d_out, int out_size) {
    const float* H  = (const float*)d_in[0];
    const void*  bt = d_in[1];
    const float* Wp = (const float*)d_in[2];
    const float* bp = (const float*)d_in[3];
    const float* ws = (const float*)d_in[4];
    float* out = (float*)d_out;

    int V = in_sizes[1];
    int nTiles = (V + TILE - 1) / TILE;

    cudaFuncSetAttribute(k1_tc, cudaFuncAttributeMaxDynamicSharedMemorySize,
                         SMEM1_TOTAL);

    k_prep<<<(out_size + 255) / 256, 256>>>(Wp, bt, V, out, out_size);
    k1_tc<<<NCTA, NTHR, SMEM1_TOTAL>>>(H, bt, bp, ws, out, V, nTiles);
    k_div<<<(out_size + 255) / 256, 256>>>(out, out_size);
}

// round 13
// speedup vs baseline: 1.6290x; 1.0157x over previous
#include <cuda_runtime.h>
#include <cuda_fp16.h>
#include <cstdint>

#define D    128
#define HS   128
#define MAXG 16384
#define AP   136      // padded smem row pitch in fp16 elems
#define TILE 64       // rows per tile (3 CTAs per SM)
#define NCTA 444
#define NTHR 192      // 4 consumer warps + 2 producer warps

// ---------------- device scratch ----------------
__device__ float g_den[MAXG];
__device__ int   g_is64;
__device__ __align__(16) __half g_Wh[HS * D];

// ---------------- smem layout (bytes) ----------------
#define SM_BW    0                       // 128 half2 (bias, w) = 512
#define SM_SE    512                     // 2 x 64 f32 = 512
#define SM_BAT0  1024                    // 64 int = 256
#define SM_BAT1  1280                    // 64 int = 256
#define SM_BHI   1536                    // 128 x AP fp16 = 34816
#define SM_A0    (SM_BHI + 34816)        // 36352  (64 x AP fp16 = 17408)
#define SM_A1    (SM_A0 + 17408)         // 53760
#define SMEM1_TOTAL (SM_A1 + 17408)      // 71168  (x3 = 213504 <= 228KB)

// ---------------- helpers ----------------
__device__ __forceinline__ unsigned su32(const void* p) {
    return (unsigned)__cvta_generic_to_shared(p);
}
__device__ __forceinline__ float tanh_approx(float x) {
    float y;
    asm("tanh.approx.f32 %0, %1;" : "=f"(y) : "f"(x));
    return y;
}

#define LDSM4(r0, r1, r2, r3, addr)                                          \
    asm volatile("ldmatrix.sync.aligned.m8n8.x4.shared.b16 {%0,%1,%2,%3}, [%4];" \
                 : "=r"(r0), "=r"(r1), "=r"(r2), "=r"(r3) : "r"(addr))

#define MMA16816F(c, a0, a1, a2, a3, b0, b1)                                 \
    asm volatile(                                                            \
        "mma.sync.aligned.m16n8k16.row.col.f32.f16.f16.f32 "                 \
        "{%0,%1,%2,%3},{%4,%5,%6,%7},{%8,%9},{%0,%1,%2,%3};"                 \
        : "+f"(c[0]), "+f"(c[1]), "+f"(c[2]), "+f"(c[3])                     \
        : "r"(a0), "r"(a1), "r"(a2), "r"(a3), "r"(b0), "r"(b1))

// ---------------- K_prep: W -> fp16 + batch dtype flag (zeroing is memset) -
__global__ void k_prep(const float* __restrict__ W,
                       const void* __restrict__ bt, int V) {
    int i = blockIdx.x * 256 + threadIdx.x;
    if (i < HS * D) g_Wh[i] = __float2half_rn(W[i]);
    if (i == 0)
        g_is64 = (((const unsigned long long*)bt)[V / 2 - 1] < (1ULL << 31)) ? 1 : 0;
}

// ---------------- staging: TILE x 128 fp32 -> fp16 (packed cvt) -----------
__device__ __forceinline__ void stage_tile(char* smem, const float* __restrict__ H,
                                           long tile, int buf, int V,
                                           int tpart, int npart) {
    __half* dst = (__half*)(smem + (buf ? SM_A1 : SM_A0));
    for (int idx = tpart; idx < TILE * 16; idx += npart) {
        int row = idx >> 4;
        int k8  = (idx & 15) << 3;
        long gr = tile * TILE + row;
        float4 v0 = make_float4(0.f, 0.f, 0.f, 0.f), v1 = v0;
        if (gr < (long)V) {
            const float4* p = (const float4*)(H + (size_t)gr * D + k8);
            v0 = p[0];
            v1 = p[1];
        }
        __half2 h0 = __float22half2_rn(make_float2(v0.x, v0.y));
        __half2 h1 = __float22half2_rn(make_float2(v0.z, v0.w));
        __half2 h2 = __float22half2_rn(make_float2(v1.x, v1.y));
        __half2 h3 = __float22half2_rn(make_float2(v1.z, v1.w));
        uint4 pack = make_uint4(*(unsigned*)&h0, *(unsigned*)&h1,
                                *(unsigned*)&h2, *(unsigned*)&h3);
        *(uint4*)(dst + row * AP + k8) = pack;
    }
}

__device__ __forceinline__ void stage_bat(char* smem, const void* __restrict__ bt,
                                          long tile, int buf, int V, int is64,
                                          int tpart) {
    // tpart in [0,TILE)
    int* dst = (int*)(smem + (buf ? SM_BAT1 : SM_BAT0));
    long gr = tile * TILE + tpart;
    int g = -1;
    if (gr < (long)V)
        g = is64 ? (int)((const long long*)bt)[gr] : ((const int*)bt)[gr];
    dst[tpart] = g;
}

// ---------------- K1: persistent fp16 HMMA + fused softmax-pool -----------
// 3 CTAs per SM: epilogues overlap other CTAs' MMA phases.
__global__ __launch_bounds__(NTHR, 3) void k1_tc(const float* __restrict__ H,
                                                 const void* __restrict__ bt,
                                                 const float* __restrict__ bp,
                                                 const float* __restrict__ ws,
                                                 float* __restrict__ num,
                                                 int V, int nTiles) {
    extern __shared__ __align__(16) char smem[];
    int tid = threadIdx.x, wid = tid >> 5, lane = tid & 31;
    __half2* bw = (__half2*)(smem + SM_BW);   // (bias, w) per col
    float* se   = (float*)(smem + SM_SE);     // [2][64]

    if (tid < 128)
        bw[tid] = __floats2half2_rn(bp[tid], ws[tid]);
    int is64 = g_is64;

    // stage stationary B = fp16(W)
    for (int idx = tid; idx < 128 * 16; idx += NTHR) {
        int row = idx >> 4;
        int k8  = (idx & 15) << 3;
        uint4 vh = *(const uint4*)(g_Wh + row * D + k8);
        *(uint4*)((__half*)(smem + SM_BHI) + row * AP + k8) = vh;
    }

    int nt = 0;
    {
        int rem = nTiles - blockIdx.x;
        if (rem > 0) nt = (rem + (int)gridDim.x - 1) / (int)gridDim.x;
    }

    if (nt > 0) {
        stage_tile((char*)smem, H, (long)blockIdx.x, 0, V, tid, NTHR);
        if (tid < TILE)
            stage_bat((char*)smem, bt, (long)blockIdx.x, 0, V, is64, tid);
    }
    __syncthreads();

    // consumer geometry (warps 0-3): 2(M) x 2(N), warp tile 32 x 64
    int wm = wid >> 1, wn = wid & 1;
    int rb = wm * 32, cb = wn * 64;
    unsigned aoff = ((rb + (lane & 15)) * AP + ((lane >> 4) << 3)) * 2;
    unsigned boff =
        ((cb + (lane & 7) + ((lane >> 4) << 3)) * AP + (((lane >> 3) & 1) << 3)) * 2;
    unsigned bhi_s = su32(smem + SM_BHI) + boff;

    // consumer epilogue constants: packed (b, w) per owned column
    unsigned hw[16];
    if (wid < 4) {
#pragma unroll
        for (int q = 0; q < 8; ++q)
#pragma unroll
            for (int par = 0; par < 2; ++par) {
                int col = cb + q * 8 + (lane & 3) * 2 + par;
                hw[q * 2 + par] = *(unsigned*)&bw[col];
            }
    }

    for (int j = 0; j < nt; ++j) {
        int b = j & 1, bn = (j + 1) & 1;
        long tj = (long)blockIdx.x + (long)j * gridDim.x;
        int* sbat = (int*)(smem + (b ? SM_BAT1 : SM_BAT0));

        if (wid >= 4) {
            // producers (2 warps): stage next tile + next batch ids
            if (j + 1 < nt) {
                long tj1 = (long)blockIdx.x + (long)(j + 1) * gridDim.x;
                stage_tile((char*)smem, H, tj1, bn, V, tid - 128, 64);
                if (tid - 128 < TILE)
                    stage_bat((char*)smem, bt, tj1, bn, V, is64, tid - 128);
            }
        } else {
            unsigned a_s = su32(smem + (b ? SM_A1 : SM_A0)) + aoff;

            float acc[2][8][4];
#pragma unroll
            for (int s = 0; s < 2; s++)
#pragma unroll
                for (int q = 0; q < 8; q++)
#pragma unroll
                    for (int c = 0; c < 4; c++) acc[s][q][c] = 0.f;

#pragma unroll
            for (int kk = 0; kk < 8; ++kk) {
                unsigned ah[2][4], bh[16];
#pragma unroll
                for (int s = 0; s < 2; ++s)
                    LDSM4(ah[s][0], ah[s][1], ah[s][2], ah[s][3],
                          a_s + kk * 32 + s * (16 * AP * 2));
#pragma unroll
                for (int p = 0; p < 4; ++p)
                    LDSM4(bh[4 * p], bh[4 * p + 1], bh[4 * p + 2], bh[4 * p + 3],
                          bhi_s + kk * 32 + p * (16 * AP * 2));
#pragma unroll
                for (int s = 0; s < 2; ++s)
#pragma unroll
                    for (int q = 0; q < 8; ++q) {
                        int bi = (q >> 1) * 4 + ((q & 1) << 1);
                        MMA16816F(acc[s][q], ah[s][0], ah[s][1], ah[s][2],
                                  ah[s][3], bh[bi], bh[bi + 1]);
                    }
            }

            // epilogue part 1: tanh-dot -> se
            float ps[4] = {0.f, 0.f, 0.f, 0.f};
#pragma unroll
            for (int s = 0; s < 2; ++s)
#pragma unroll
                for (int q = 0; q < 8; ++q)
#pragma unroll
                    for (int e = 0; e < 4; ++e) {
                        __half2 hv = *(__half2*)&hw[q * 2 + (e & 1)];
                        float2 bwf = __half22float2(hv);
                        float z = acc[s][q][e] + bwf.x;
                        ps[s * 2 + (e >> 1)] += tanh_approx(z) * bwf.y;
                    }
#pragma unroll
            for (int q = 0; q < 4; ++q) {
                ps[q] += __shfl_xor_sync(0xffffffffu, ps[q], 1);
                ps[q] += __shfl_xor_sync(0xffffffffu, ps[q], 2);
            }
            if ((lane & 3) == 0) {
#pragma unroll
                for (int q = 0; q < 4; ++q) {
                    int r = rb + (q >> 1) * 16 + (lane >> 2) + (q & 1) * 8;
                    se[wn * 64 + r] = ps[q];
                }
            }
            asm volatile("bar.sync 1, 128;" ::: "memory");

            // epilogue part 2: pooling with inline exp (no max shift needed:
            // |e| <= ||w||_1 ~ 9). Warp w owns rows [16w,16w+16); lane: 4 cols.
            {
                const __half* hh = (const __half*)(smem + (b ? SM_A1 : SM_A0));
                int r0 = wid * 16;
                int d4 = lane * 4;
                float pacc0 = 0.f, pacc1 = 0.f, pacc2 = 0.f, pacc3 = 0.f;
                float psum = 0.f;
                int g = sbat[r0];
#pragma unroll
                for (int rr = 0; rr < 16; ++rr) {
                    int r = r0 + rr;
                    int gr = sbat[r];
                    if (gr != g) {
                        if (g >= 0) {
                            float* dst = num + (size_t)g * D + d4;
                            atomicAdd(dst + 0, pacc0);
                            atomicAdd(dst + 1, pacc1);
                            atomicAdd(dst + 2, pacc2);
                            atomicAdd(dst + 3, pacc3);
                            if (lane == 0) atomicAdd(g_den + g, psum);
                        }
                        pacc0 = pacc1 = pacc2 = pacc3 = 0.f;
                        psum = 0.f;
                        g = gr;
                    }
                    float p = __expf(se[r] + se[64 + r]);
                    uint2 vh = *(const uint2*)(hh + r * AP + d4);
                    __half2 h0 = *(__half2*)&vh.x, h1 = *(__half2*)&vh.y;
                    float2 f0 = __half22float2(h0), f1 = __half22float2(h1);
                    pacc0 += p * f0.x;
                    pacc1 += p * f0.y;
                    pacc2 += p * f1.x;
                    pacc3 += p * f1.y;
                    psum += p;
                }
                if (g >= 0) {
                    float* dst = num + (size_t)g * D + d4;
                    atomicAdd(dst + 0, pacc0);
                    atomicAdd(dst + 1, pacc1);
                    atomicAdd(dst + 2, pacc2);
                    atomicAdd(dst + 3, pacc3);
                    if (lane == 0) atomicAdd(g_den + g, psum);
                }
            }
        }
        __syncthreads();
    }
}

// ---------------- K_div: out = num / max(den, 1e-12), float4 --------------
__global__ void k_div(float4* __restrict__ out, int n4) {
    int i = blockIdx.x * 256 + threadIdx.x;
    if (i < n4) {
        float inv = 1.0f / fmaxf(g_den[i >> 5], 1e-12f);
        float4 v = out[i];
        v.x *= inv; v.y *= inv; v.z *= inv; v.w *= inv;
        out[i] = v;
    }
}

// ---------------- launch ----------------
extern "C" void kernel_launch(void* const* d_in, const int* in_sizes, int n_in,
                              void* d_out, int out_size) {
    const float* H  = (const float*)d_in[0];
    const void*  bt = d_in[1];
    const float* Wp = (const float*)d_in[2];
    const float* bp = (const float*)d_in[3];
    const float* ws = (const float*)d_in[4];
    float* out = (float*)d_out;

    int V = in_sizes[1];
    int nTiles = (V + TILE - 1) / TILE;

    cudaFuncSetAttribute(k1_tc, cudaFuncAttributeMaxDynamicSharedMemorySize,
                         SMEM1_TOTAL);

    // async, graph-capturable zeroing (no allocation)
    cudaMemsetAsync(out, 0, (size_t)out_size * sizeof(float));
    void* denp = nullptr;
    cudaGetSymbolAddress(&denp, g_den);
    cudaMemsetAsync(denp, 0, MAXG * sizeof(float));

    k_prep<<<(HS * D + 255) / 256, 256>>>(Wp, bt, V);
    k1_tc<<<NCTA, NTHR, SMEM1_TOTAL>>>(H, bt, bp, ws, out, V, nTiles);
    int n4 = out_size / 4;
    k_div<<<(n4 + 255) / 256, 256>>>((float4*)out, n4);
}

// round 14
// speedup vs baseline: 1.7068x; 1.0478x over previous
#include <cuda_runtime.h>
#include <cuda_fp16.h>
#include <cstdint>

#define D    128
#define HS   128
#define MAXG 16384
#define AP   136      // padded smem row pitch in fp16 elems
#define TILE 64       // rows per tile (4 CTAs per SM)
#define NCTA 592
#define NTHR 128      // 4 warps, no specialization

// ---------------- device scratch ----------------
__device__ float g_den[MAXG];

// ---------------- smem layout (bytes) ----------------
#define SM_BW    0                       // 128 half2 (bias, w) = 512
#define SM_SE    512                     // 2 x 64 f32 = 512
#define SM_BAT   1024                    // 64 int = 256
#define SM_BHI   1536                    // 128 x AP fp16 = 34816
#define SM_A0    (SM_BHI + 34816)        // 36352  (64 x AP fp16 = 17408)
#define SMEM1_TOTAL (SM_A0 + 17408)      // 53760  (x4 = 215040 <= 228KB)

// ---------------- helpers ----------------
__device__ __forceinline__ unsigned su32(const void* p) {
    return (unsigned)__cvta_generic_to_shared(p);
}
__device__ __forceinline__ float tanh_approx(float x) {
    float y;
    asm("tanh.approx.f32 %0, %1;" : "=f"(y) : "f"(x));
    return y;
}

#define LDSM4(r0, r1, r2, r3, addr)                                          \
    asm volatile("ldmatrix.sync.aligned.m8n8.x4.shared.b16 {%0,%1,%2,%3}, [%4];" \
                 : "=r"(r0), "=r"(r1), "=r"(r2), "=r"(r3) : "r"(addr))

#define MMA16816F(c, a0, a1, a2, a3, b0, b1)                                 \
    asm volatile(                                                            \
        "mma.sync.aligned.m16n8k16.row.col.f32.f16.f16.f32 "                 \
        "{%0,%1,%2,%3},{%4,%5,%6,%7},{%8,%9},{%0,%1,%2,%3};"                 \
        : "+f"(c[0]), "+f"(c[1]), "+f"(c[2]), "+f"(c[3])                     \
        : "r"(a0), "r"(a1), "r"(a2), "r"(a3), "r"(b0), "r"(b1))

// ---------------- staging: TILE x 128 fp32 -> fp16 (packed cvt) -----------
__device__ __forceinline__ void stage_tile(char* smem, const float* __restrict__ H,
                                           long tile, int V, int tpart) {
    __half* dst = (__half*)(smem + SM_A0);
    for (int idx = tpart; idx < TILE * 16; idx += NTHR) {
        int row = idx >> 4;
        int k8  = (idx & 15) << 3;
        long gr = tile * TILE + row;
        float4 v0 = make_float4(0.f, 0.f, 0.f, 0.f), v1 = v0;
        if (gr < (long)V) {
            const float4* p = (const float4*)(H + (size_t)gr * D + k8);
            v0 = p[0];
            v1 = p[1];
        }
        __half2 h0 = __float22half2_rn(make_float2(v0.x, v0.y));
        __half2 h1 = __float22half2_rn(make_float2(v0.z, v0.w));
        __half2 h2 = __float22half2_rn(make_float2(v1.x, v1.y));
        __half2 h3 = __float22half2_rn(make_float2(v1.z, v1.w));
        uint4 pack = make_uint4(*(unsigned*)&h0, *(unsigned*)&h1,
                                *(unsigned*)&h2, *(unsigned*)&h3);
        *(uint4*)(dst + row * AP + k8) = pack;
    }
}

// ---------------- K1: persistent fp16 HMMA + fused softmax-pool -----------
// 4 CTAs per SM, no warp specialization: 4 independent MMA streams per SMSP.
__global__ __launch_bounds__(NTHR, 4) void k1_tc(const float* __restrict__ H,
                                                 const void* __restrict__ bt,
                                                 const float* __restrict__ Wp,
                                                 const float* __restrict__ bp,
                                                 const float* __restrict__ ws,
                                                 float* __restrict__ num,
                                                 int V, int nTiles) {
    extern __shared__ __align__(16) char smem[];
    int tid = threadIdx.x, wid = tid >> 5, lane = tid & 31;
    __half2* bw = (__half2*)(smem + SM_BW);   // (bias, w) per col
    float* se   = (float*)(smem + SM_SE);     // [2][64]
    int* sbat   = (int*)(smem + SM_BAT);      // [64]

    bw[tid] = __floats2half2_rn(bp[tid], ws[tid]);
    bool is64 = (((const unsigned long long*)bt)[V / 2 - 1] < (1ULL << 31));

    // stage stationary B = fp16(W) straight from fp32 global
    for (int idx = tid; idx < 128 * 16; idx += NTHR) {
        int row = idx >> 4;
        int k8  = (idx & 15) << 3;
        const float4* p = (const float4*)(Wp + row * D + k8);
        float4 v0 = p[0], v1 = p[1];
        __half2 h0 = __float22half2_rn(make_float2(v0.x, v0.y));
        __half2 h1 = __float22half2_rn(make_float2(v0.z, v0.w));
        __half2 h2 = __float22half2_rn(make_float2(v1.x, v1.y));
        __half2 h3 = __float22half2_rn(make_float2(v1.z, v1.w));
        uint4 pack = make_uint4(*(unsigned*)&h0, *(unsigned*)&h1,
                                *(unsigned*)&h2, *(unsigned*)&h3);
        *(uint4*)((__half*)(smem + SM_BHI) + row * AP + k8) = pack;
    }

    int nt = 0;
    {
        int rem = nTiles - blockIdx.x;
        if (rem > 0) nt = (rem + (int)gridDim.x - 1) / (int)gridDim.x;
    }

    // geometry: 2(M) x 2(N), warp tile 32 x 64
    int wm = wid >> 1, wn = wid & 1;
    int rb = wm * 32, cb = wn * 64;
    unsigned aoff = ((rb + (lane & 15)) * AP + ((lane >> 4) << 3)) * 2;
    unsigned boff =
        ((cb + (lane & 7) + ((lane >> 4) << 3)) * AP + (((lane >> 3) & 1) << 3)) * 2;
    unsigned bhi_s = su32(smem + SM_BHI) + boff;
    unsigned a_s = su32(smem + SM_A0) + aoff;

    // epilogue constants: packed (b, w) per owned column
    unsigned hw[16];
#pragma unroll
    for (int q = 0; q < 8; ++q)
#pragma unroll
        for (int par = 0; par < 2; ++par) {
            int col = cb + q * 8 + (lane & 3) * 2 + par;
            hw[q * 2 + par] = *(unsigned*)&bw[col];
        }
    __syncthreads();  // bw ready (stage_tile below also needs nothing else)

    for (int j = 0; j < nt; ++j) {
        long tj = (long)blockIdx.x + (long)j * gridDim.x;

        // phase 1: stage A tile + batch ids (all warps)
        stage_tile((char*)smem, H, tj, V, tid);
        if (tid < TILE) {
            long gr = tj * TILE + tid;
            int g = -1;
            if (gr < (long)V)
                g = is64 ? (int)((const long long*)bt)[gr]
                         : ((const int*)bt)[gr];
            sbat[tid] = g;
        }
        __syncthreads();

        // phase 2: MMA
        float acc[2][8][4];
#pragma unroll
        for (int s = 0; s < 2; s++)
#pragma unroll
            for (int q = 0; q < 8; q++)
#pragma unroll
                for (int c = 0; c < 4; c++) acc[s][q][c] = 0.f;

#pragma unroll
        for (int kk = 0; kk < 8; ++kk) {
            unsigned ah[2][4], bh[16];
#pragma unroll
            for (int s = 0; s < 2; ++s)
                LDSM4(ah[s][0], ah[s][1], ah[s][2], ah[s][3],
                      a_s + kk * 32 + s * (16 * AP * 2));
#pragma unroll
            for (int p = 0; p < 4; ++p)
                LDSM4(bh[4 * p], bh[4 * p + 1], bh[4 * p + 2], bh[4 * p + 3],
                      bhi_s + kk * 32 + p * (16 * AP * 2));
#pragma unroll
            for (int s = 0; s < 2; ++s)
#pragma unroll
                for (int q = 0; q < 8; ++q) {
                    int bi = (q >> 1) * 4 + ((q & 1) << 1);
                    MMA16816F(acc[s][q], ah[s][0], ah[s][1], ah[s][2],
                              ah[s][3], bh[bi], bh[bi + 1]);
                }
        }

        // phase 3: tanh-dot -> se
        float ps[4] = {0.f, 0.f, 0.f, 0.f};
#pragma unroll
        for (int s = 0; s < 2; ++s)
#pragma unroll
            for (int q = 0; q < 8; ++q)
#pragma unroll
                for (int e = 0; e < 4; ++e) {
                    __half2 hv = *(__half2*)&hw[q * 2 + (e & 1)];
                    float2 bwf = __half22float2(hv);
                    float z = acc[s][q][e] + bwf.x;
                    ps[s * 2 + (e >> 1)] += tanh_approx(z) * bwf.y;
                }
#pragma unroll
        for (int q = 0; q < 4; ++q) {
            ps[q] += __shfl_xor_sync(0xffffffffu, ps[q], 1);
            ps[q] += __shfl_xor_sync(0xffffffffu, ps[q], 2);
        }
        if ((lane & 3) == 0) {
#pragma unroll
            for (int q = 0; q < 4; ++q) {
                int r = rb + (q >> 1) * 16 + (lane >> 2) + (q & 1) * 8;
                se[wn * 64 + r] = ps[q];
            }
        }
        __syncthreads();

        // phase 4: pooling with inline exp (no max shift: |e| <= ||w||_1 ~ 9).
        // Warp w owns rows [16w,16w+16); lane owns 4 d-cols.
        {
            const __half* hh = (const __half*)(smem + SM_A0);
            int r0 = wid * 16;
            int d4 = lane * 4;
            float pacc0 = 0.f, pacc1 = 0.f, pacc2 = 0.f, pacc3 = 0.f;
            float psum = 0.f;
            int g = sbat[r0];
#pragma unroll
            for (int rr = 0; rr < 16; ++rr) {
                int r = r0 + rr;
                int gr = sbat[r];
                if (gr != g) {
                    if (g >= 0) {
                        float* dst = num + (size_t)g * D + d4;
                        atomicAdd(dst + 0, pacc0);
                        atomicAdd(dst + 1, pacc1);
                        atomicAdd(dst + 2, pacc2);
                        atomicAdd(dst + 3, pacc3);
                        if (lane == 0) atomicAdd(g_den + g, psum);
                    }
                    pacc0 = pacc1 = pacc2 = pacc3 = 0.f;
                    psum = 0.f;
                    g = gr;
                }
                float p = __expf(se[r] + se[64 + r]);
                uint2 vh = *(const uint2*)(hh + r * AP + d4);
                __half2 h0 = *(__half2*)&vh.x, h1 = *(__half2*)&vh.y;
                float2 f0 = __half22float2(h0), f1 = __half22float2(h1);
                pacc0 += p * f0.x;
                pacc1 += p * f0.y;
                pacc2 += p * f1.x;
                pacc3 += p * f1.y;
                psum += p;
            }
            if (g >= 0) {
                float* dst = num + (size_t)g * D + d4;
                atomicAdd(dst + 0, pacc0);
                atomicAdd(dst + 1, pacc1);
                atomicAdd(dst + 2, pacc2);
                atomicAdd(dst + 3, pacc3);
                if (lane == 0) atomicAdd(g_den + g, psum);
            }
        }
        __syncthreads();
    }
}

// ---------------- K_div: out = num / max(den, 1e-12), float4 --------------
__global__ void k_div(float4* __restrict__ out, int n4) {
    int i = blockIdx.x * 256 + threadIdx.x;
    if (i < n4) {
        float inv = 1.0f / fmaxf(g_den[i >> 5], 1e-12f);
        float4 v = out[i];
        v.x *= inv; v.y *= inv; v.z *= inv; v.w *= inv;
        out[i] = v;
    }
}

// ---------------- launch ----------------
extern "C" void kernel_launch(void* const* d_in, const int* in_sizes, int n_in,
                              void* d_out, int out_size) {
    const float* H  = (const float*)d_in[0];
    const void*  bt = d_in[1];
    const float* Wp = (const float*)d_in[2];
    const float* bp = (const float*)d_in[3];
    const float* ws = (const float*)d_in[4];
    float* out = (float*)d_out;

    int V = in_sizes[1];
    int nTiles = (V + TILE - 1) / TILE;

    cudaFuncSetAttribute(k1_tc, cudaFuncAttributeMaxDynamicSharedMemorySize,
                         SMEM1_TOTAL);

    // async, graph-capturable zeroing (no allocation)
    cudaMemsetAsync(out, 0, (size_t)out_size * sizeof(float));
    void* denp = nullptr;
    cudaGetSymbolAddress(&denp, g_den);
    cudaMemsetAsync(denp, 0, MAXG * sizeof(float));

    k1_tc<<<NCTA, NTHR, SMEM1_TOTAL>>>(H, bt, Wp, bp, ws, out, V, nTiles);
    int n4 = out_size / 4;
    k_div<<<(n4 + 255) / 256, 256>>>((float4*)out, n4);
}